// round 11
// baseline (speedup 1.0000x reference)
#include <cuda_runtime.h>
#include <math.h>

// Problem shape (fixed by the dataset)
#define B_DIM 48
#define T_DIM 5000
#define F_DIM 161
#define BT (B_DIM * T_DIM)                  // 240000 rows
#define NEW_MAG_ELEMS ((size_t)BT * F_DIM)  // 38,640,000

#define CHUNK 200                  // frames per chunk (divides 5000, mult of 4)
#define CHUNKS_PB (T_DIM / CHUNK)  // 25 chunks per batch
#define NBLK (B_DIM * CHUNKS_PB)   // 1200 blocks
#define THREADS 512
#define CHUNK_ELEMS (CHUNK * F_DIM)  // 32200
#define CHUNK_F4 (CHUNK_ELEMS / 4)   // 8050 (exact; chunk base 16B-aligned)
#define NGROUPS (CHUNK / 4)          // 50 four-row groups, 161 float4s each

// Scratch (no cudaMalloc). Recomputed every launch — replay-safe, no init.
__device__ float g_Apre[BT];          // within-chunk prefix map A (per row)
__device__ float g_Bpre[BT];          // within-chunk prefix map B (per row)
__device__ float g_carryv[NBLK];      // incoming g-value for each (b,c)

// ---------------------------------------------------------------------------
// Kernel A: per-row power -> x, then per-chunk local affine scan.
// No inter-block dependencies. Pure read stream.
// ---------------------------------------------------------------------------
__global__ void __launch_bounds__(THREADS) k_power_scan(
    const float* __restrict__ mag)
{
    __shared__ float sx[CHUNK];

    int tid = threadIdx.x;
    int wid = tid >> 5, lane = tid & 31;
    int vid = blockIdx.x;
    int b = vid / CHUNKS_PB;
    int c = vid % CHUNKS_PB;

    size_t row0 = (size_t)b * T_DIM + (size_t)c * CHUNK;
    const float* base = mag + row0 * F_DIM;

    // ---- per-4-row-group power, flat float4 loads (coalesced) ----
    for (int g = wid; g < NGROUPS; g += THREADS / 32) {
        const float4* m4 = (const float4*)base + g * F_DIM;  // 161 float4s
        float s0 = 0.f, s1 = 0.f, s2 = 0.f, s3 = 0.f;
        #pragma unroll
        for (int it = 0; it < 6; it++) {
            int j = it * 32 + lane;
            if (j < F_DIM) {
                float4 v = m4[j];
                unsigned e = (unsigned)j * 4u;
                unsigned lr = (e >= 322u) ? ((e >= 483u) ? 3u : 2u)
                                          : ((e >= 161u) ? 1u : 0u);
                unsigned rem = e - lr * 161u;
                float sq = fmaf(v.x, v.x, fmaf(v.y, v.y,
                              fmaf(v.z, v.z, v.w * v.w)));
                if (rem <= 157u) {
                    if      (lr == 0) s0 += sq;
                    else if (lr == 1) s1 += sq;
                    else if (lr == 2) s2 += sq;
                    else              s3 += sq;
                } else {
                    float ay = v.y * v.y, az = v.z * v.z, aw = v.w * v.w;
                    bool b1 = rem + 1 < 161u, b2 = rem + 2 < 161u, b3 = rem + 3 < 161u;
                    float lo = v.x * v.x + (b1 ? ay : 0.f) + (b2 ? az : 0.f) + (b3 ? aw : 0.f);
                    float hi = sq - lo;
                    if      (lr == 0) { s0 += lo; s1 += hi; }
                    else if (lr == 1) { s1 += lo; s2 += hi; }
                    else              { s2 += lo; s3 += hi; }
                }
            }
        }
        #pragma unroll
        for (int off = 16; off > 0; off >>= 1) {
            s0 += __shfl_xor_sync(0xffffffffu, s0, off);
            s1 += __shfl_xor_sync(0xffffffffu, s1, off);
            s2 += __shfl_xor_sync(0xffffffffu, s2, off);
            s3 += __shfl_xor_sync(0xffffffffu, s3, off);
        }
        if (lane < 4) {
            float sum = (lane == 0) ? s0 : (lane == 1) ? s1 : (lane == 2) ? s2 : s3;
            int r = g * 4 + lane;
            float m0 = base[(size_t)r * F_DIM];            // L1 hits
            float mN = base[(size_t)r * F_DIM + F_DIM - 1];
            float sp = (2.0f * sum - m0 * m0 - mN * mN) * (1.0f / 320.0f);
            sx[r] = sqrtf(sp);
        }
    }
    __syncthreads();

    // ---- warp 0: local affine scan; write per-row prefix maps to global ----
    if (wid == 0) {
        float cA = 1.0f, cB = 0.0f;
        int t_base = c * CHUNK;
        #pragma unroll
        for (int w = 0; w < (CHUNK + 31) / 32; w++) {
            int r = w * 32 + lane;
            float A, Bv;
            if (r < CHUNK) {
                float xv = sx[r];
                if (t_base + r == 0) { A = 0.0f; Bv = xv; }
                else                 { A = 0.9f; Bv = 0.1f * xv; }
            } else { A = 1.0f; Bv = 0.0f; }

            #pragma unroll
            for (int off = 1; off < 32; off <<= 1) {
                float Ap = __shfl_up_sync(0xffffffffu, A, off);
                float Bp = __shfl_up_sync(0xffffffffu, Bv, off);
                if (lane >= off) { Bv = fmaf(A, Bp, Bv); A *= Ap; }
            }
            float Apre = A * cA;
            float Bpre = fmaf(A, cB, Bv);
            if (r < CHUNK) {
                g_Apre[row0 + r] = Apre;
                g_Bpre[row0 + r] = Bpre;
            }
            cA = __shfl_sync(0xffffffffu, Apre, 31);
            cB = __shfl_sync(0xffffffffu, Bpre, 31);
        }
    }
}

// ---------------------------------------------------------------------------
// Kernel A2: per-batch scan over chunk-end compositions -> incoming carries.
// 48 blocks x 32 threads; trivially fast.
// ---------------------------------------------------------------------------
__global__ void k_chunk_scan() {
    int b = blockIdx.x;
    int lane = threadIdx.x;

    float A = 1.0f, Bv = 0.0f;
    if (lane < CHUNKS_PB) {
        size_t lastrow = (size_t)b * T_DIM + (size_t)lane * CHUNK + CHUNK - 1;
        A = g_Apre[lastrow];
        Bv = g_Bpre[lastrow];
    }
    #pragma unroll
    for (int off = 1; off < 32; off <<= 1) {
        float Ap = __shfl_up_sync(0xffffffffu, A, off);
        float Bp = __shfl_up_sync(0xffffffffu, Bv, off);
        if (lane >= off) { Bv = fmaf(A, Bp, Bv); A *= Ap; }
    }
    // carry for chunk (lane+1) = g at end of chunk lane = inclusive B
    if (lane < CHUNKS_PB - 1) g_carryv[b * CHUNKS_PB + lane + 1] = Bv;
    if (lane == 0)            g_carryv[b * CHUNKS_PB] = 0.0f;
}

// ---------------------------------------------------------------------------
// Kernel B: gains + new_mag. No inter-block dependencies; pure stream.
// ---------------------------------------------------------------------------
__global__ void __launch_bounds__(THREADS) k_apply(
    const float* __restrict__ mag,
    float* __restrict__ out,
    float* __restrict__ out_gain)
{
    __shared__ float sinv[CHUNK];

    int tid = threadIdx.x;
    int vid = blockIdx.x;
    int b = vid / CHUNKS_PB;
    int c = vid % CHUNKS_PB;

    size_t row0 = (size_t)b * T_DIM + (size_t)c * CHUNK;
    float carry = g_carryv[vid];       // broadcast, L1/L2 hit

    if (tid < CHUNK) {
        float g = fmaf(g_Apre[row0 + tid], carry, g_Bpre[row0 + tid]);
        out_gain[row0 + tid] = g;
        sinv[tid] = 1.0f / (g + 0.001f);
    }
    __syncthreads();

    const float4* m4 = (const float4*)(mag + row0 * F_DIM);
    float4* o4 = (float4*)(out + row0 * F_DIM);
    #pragma unroll 4
    for (int i = tid; i < CHUNK_F4; i += THREADS) {
        float4 v = m4[i];
        unsigned e0 = (unsigned)i * 4u;
        unsigned r0 = e0 / F_DIM;              // const-div -> mulhi
        unsigned rem = e0 - r0 * F_DIM;
        float inv0 = sinv[r0];
        float inv1 = (rem > (unsigned)(F_DIM - 4)) ? sinv[r0 + 1] : inv0;
        float4 rr;
        rr.x = v.x * inv0;
        rr.y = v.y * ((rem + 1 < F_DIM) ? inv0 : inv1);
        rr.z = v.z * ((rem + 2 < F_DIM) ? inv0 : inv1);
        rr.w = v.w * ((rem + 3 < F_DIM) ? inv0 : inv1);
        o4[i] = rr;
    }
}

// ---------------------------------------------------------------------------
extern "C" void kernel_launch(void* const* d_in, const int* in_sizes, int n_in,
                              void* d_out, int out_size) {
    const float* mag = (const float*)d_in[0];
    float* out = (float*)d_out;
    float* out_gain = out + NEW_MAG_ELEMS;

    k_power_scan<<<NBLK, THREADS>>>(mag);
    k_chunk_scan<<<B_DIM, 32>>>();
    k_apply<<<NBLK, THREADS>>>(mag, out, out_gain);
}

// round 13
// speedup vs baseline: 1.1148x; 1.1148x over previous
#include <cuda_runtime.h>
#include <math.h>

// Problem shape (fixed by the dataset)
#define B_DIM 48
#define T_DIM 5000
#define F_DIM 161
#define BT (B_DIM * T_DIM)                  // 240000 rows
#define NEW_MAG_ELEMS ((size_t)BT * F_DIM)  // 38,640,000

#define CHUNK 500                   // frames per block
#define CPB (T_DIM / CHUNK)         // 10 chunks per batch
#define NBLK (B_DIM * CPB)          // 480 blocks (~single wave @ 3/SM)
#define THREADS 512
#define SUB 100                     // frames per smem sub-tile
#define NSUB (CHUNK / SUB)          // 5 sub-tiles
#define SUB_ELEMS (SUB * F_DIM)     // 16100
#define SUB_F4 (SUB_ELEMS / 4)      // 4025 (exact; sub-tile base 16B-aligned)
#define WARM 200                    // warmup rows (0.9^200 ~ 7e-10 << 1e-3 tol)

#define LOG2_09 (-0.15200309344504997f)

// smem layout (floats): tile[16100] | sx[100] | sA[100] | sB[100] | red[17]
#define SMEM_FLOATS (SUB_ELEMS + 3 * SUB + 17)
#define SMEM_BYTES (SMEM_FLOATS * 4)

__global__ void __launch_bounds__(THREADS) k_agc(
    const float* __restrict__ mag,
    float* __restrict__ out,
    float* __restrict__ out_gain)
{
    extern __shared__ float smem[];
    float* tile = smem;                 // SUB_ELEMS
    float* sx   = smem + SUB_ELEMS;     // SUB (aliased as sinv after scan)
    float* sA   = sx + SUB;             // SUB
    float* sB   = sA + SUB;             // SUB
    float* red  = sB + SUB;             // 17 (16 warp sums + carry slot)

    int tid = threadIdx.x;
    int wid = tid >> 5, lane = tid & 31;
    int b = blockIdx.x / CPB;
    int c = blockIdx.x % CPB;
    int row0 = b * T_DIM + c * CHUNK;   // global row of chunk start

    float carry = 0.0f;

    // ---- warmup: weighted reduction over the 200 rows before the chunk ----
    // carry = g_{row0-1} ~= sum_w 0.1 * 0.9^(WARM-1-w) * x[row0-WARM+w]
    // (c>0 guarantees warmup rows lie inside the same batch)
    if (c > 0) {
        float* sxw = sA;   // 200 contiguous floats across sA|sB
        for (int r = wid; r < WARM; r += THREADS / 32) {
            const float* m = mag + (size_t)(row0 - WARM + r) * F_DIM;
            float s = 0.0f;
            #pragma unroll
            for (int f = lane; f < F_DIM; f += 32) {
                float v = m[f];
                s = fmaf(v, v, s);
            }
            #pragma unroll
            for (int off = 16; off > 0; off >>= 1)
                s += __shfl_xor_sync(0xffffffffu, s, off);
            if (lane == 0) {
                float m0 = m[0];
                float mN = m[F_DIM - 1];
                float sp = (2.0f * s - m0 * m0 - mN * mN) * (1.0f / 320.0f);
                sxw[r] = sqrtf(sp);
            }
        }
        __syncthreads();

        float v = 0.0f;
        if (tid < WARM)
            v = sxw[tid] * 0.1f * exp2f((float)(WARM - 1 - tid) * LOG2_09);
        #pragma unroll
        for (int off = 16; off > 0; off >>= 1)
            v += __shfl_xor_sync(0xffffffffu, v, off);
        if (lane == 0) red[wid] = v;
        __syncthreads();
        if (tid == 0) {
            float s = 0.0f;
            #pragma unroll
            for (int w = 0; w < THREADS / 32; w++) s += red[w];
            red[16] = s;
        }
        __syncthreads();
        carry = red[16];
        __syncthreads();   // sA/sB free for reuse
    }

    // ---- 5 sub-tiles: load -> power -> scan -> gains -> multiply ----
    for (int sub = 0; sub < NSUB; sub++) {
        int srow = row0 + sub * SUB;        // global row of sub-tile start
        int t0   = c * CHUNK + sub * SUB;   // within-batch time of sub-tile start
        const float* base = mag + (size_t)srow * F_DIM;

        // load sub-tile, flat float4, coalesced
        {
            const float4* m4 = (const float4*)base;
            float4* t4 = (float4*)tile;
            #pragma unroll 4
            for (int i = tid; i < SUB_F4; i += THREADS)
                t4[i] = m4[i];
        }
        __syncthreads();

        // per-row power from smem (warp per row)
        for (int r = wid; r < SUB; r += THREADS / 32) {
            const float* m = tile + r * F_DIM;
            float s = 0.0f;
            #pragma unroll
            for (int f = lane; f < F_DIM; f += 32) {
                float v = m[f];
                s = fmaf(v, v, s);
            }
            #pragma unroll
            for (int off = 16; off > 0; off >>= 1)
                s += __shfl_xor_sync(0xffffffffu, s, off);
            if (lane == 0) {
                float m0 = m[0];
                float mN = m[F_DIM - 1];
                float sp = (2.0f * s - m0 * m0 - mN * mN) * (1.0f / 320.0f);
                sx[r] = sqrtf(sp);
            }
        }
        __syncthreads();

        // warp 0: affine scan over SUB rows (relative maps)
        if (wid == 0) {
            float cA = 1.0f, cB = 0.0f;
            #pragma unroll
            for (int w = 0; w < (SUB + 31) / 32; w++) {
                int r = w * 32 + lane;
                float A, Bv;
                if (r < SUB) {
                    float xv = sx[r];
                    if (t0 + r == 0) { A = 0.0f; Bv = xv; }  // within-batch frame 0
                    else             { A = 0.9f; Bv = 0.1f * xv; }
                } else { A = 1.0f; Bv = 0.0f; }

                #pragma unroll
                for (int off = 1; off < 32; off <<= 1) {
                    float Ap = __shfl_up_sync(0xffffffffu, A, off);
                    float Bp = __shfl_up_sync(0xffffffffu, Bv, off);
                    if (lane >= off) { Bv = fmaf(A, Bp, Bv); A *= Ap; }
                }
                float Apre = A * cA;
                float Bpre = fmaf(A, cB, Bv);
                if (r < SUB) { sA[r] = Apre; sB[r] = Bpre; }
                cA = __shfl_sync(0xffffffffu, Apre, 31);
                cB = __shfl_sync(0xffffffffu, Bpre, 31);
            }
        }
        __syncthreads();

        // gains + reciprocals (sinv aliases sx); advance carry (all threads)
        float ncarry = fmaf(sA[SUB - 1], carry, sB[SUB - 1]);
        float* sinv = sx;
        if (tid < SUB) {
            float g = fmaf(sA[tid], carry, sB[tid]);
            out_gain[srow + tid] = g;
            sinv[tid] = 1.0f / (g + 0.001f);
        }
        carry = ncarry;
        __syncthreads();

        // multiply + store, float4, one const-div per float4
        {
            const float4* t4 = (const float4*)tile;
            float4* o4 = (float4*)(out + (size_t)srow * F_DIM);
            #pragma unroll 4
            for (int i = tid; i < SUB_F4; i += THREADS) {
                float4 v = t4[i];
                unsigned e0 = (unsigned)i * 4u;
                unsigned r0 = e0 / F_DIM;            // const-div -> mulhi
                unsigned rem = e0 - r0 * F_DIM;
                float inv0 = sinv[r0];
                float inv1 = (rem > (unsigned)(F_DIM - 4)) ? sinv[r0 + 1] : inv0;
                float4 rr;
                rr.x = v.x * inv0;
                rr.y = v.y * ((rem + 1 < F_DIM) ? inv0 : inv1);
                rr.z = v.z * ((rem + 2 < F_DIM) ? inv0 : inv1);
                rr.w = v.w * ((rem + 3 < F_DIM) ? inv0 : inv1);
                o4[i] = rr;
            }
        }
        __syncthreads();   // tile consumed before next sub-tile load
    }
}

// ---------------------------------------------------------------------------
extern "C" void kernel_launch(void* const* d_in, const int* in_sizes, int n_in,
                              void* d_out, int out_size) {
    const float* mag = (const float*)d_in[0];
    float* out = (float*)d_out;
    float* out_gain = out + NEW_MAG_ELEMS;

    cudaFuncSetAttribute(k_agc, cudaFuncAttributeMaxDynamicSharedMemorySize,
                         SMEM_BYTES);
    k_agc<<<NBLK, THREADS, SMEM_BYTES>>>(mag, out, out_gain);
}

// round 15
// speedup vs baseline: 1.2157x; 1.0905x over previous
#include <cuda_runtime.h>
#include <math.h>

// Problem shape (fixed by the dataset)
#define B_DIM 48
#define T_DIM 5000
#define F_DIM 161
#define BT (B_DIM * T_DIM)                  // 240000 rows
#define NEW_MAG_ELEMS ((size_t)BT * F_DIM)  // 38,640,000

#define CHUNK 500                   // frames per block
#define CPB (T_DIM / CHUNK)         // 10 chunks per batch
#define NBLK (B_DIM * CPB)          // 480 blocks, fully independent
#define THREADS 512
#define NWARP (THREADS / 32)        // 16
#define SUBROWS 32                  // rows per sub-tile = NWARP * 2
#define NSUB ((CHUNK + SUBROWS - 1) / SUBROWS)  // 16 (15 full + one of 20)
#define WARM 200                    // warmup rows; 0.9^200 ~ 7e-10 << 1e-3

#define LOG2_09 (-0.15200309344504997f)

__global__ void __launch_bounds__(THREADS, 3) k_agc(
    const float* __restrict__ mag,
    float* __restrict__ out,
    float* __restrict__ out_gain)
{
    __shared__ float sx[2][SUBROWS];    // double-buffered per-sub-tile x values
    __shared__ float red[NWARP + 1];

    int tid = threadIdx.x;
    int wid = tid >> 5, lane = tid & 31;
    int b = blockIdx.x / CPB;
    int c = blockIdx.x % CPB;
    int row0 = b * T_DIM + c * CHUNK;   // global row of chunk start

    float carry = 0.0f;

    // ---- warmup: weighted reduction over the 200 rows before the chunk ----
    // carry ~= sum_r 0.1 * 0.9^(WARM-1-r) * x[row0-WARM+r]  (c>0 => in-batch)
    if (c > 0) {
        float acc = 0.0f;
        for (int r = wid; r < WARM; r += NWARP) {
            const float* m = mag + (size_t)(row0 - WARM + r) * F_DIM;
            float s = 0.0f;
            #pragma unroll
            for (int f = lane; f < F_DIM; f += 32) {
                float v = m[f];
                s = fmaf(v, v, s);
            }
            #pragma unroll
            for (int off = 16; off > 0; off >>= 1)
                s += __shfl_xor_sync(0xffffffffu, s, off);
            if (lane == 0) {
                float m0 = m[0];
                float mN = m[F_DIM - 1];
                float sp = (2.0f * s - m0 * m0 - mN * mN) * (1.0f / 320.0f);
                acc = fmaf(sqrtf(sp),
                           0.1f * exp2f((float)(WARM - 1 - r) * LOG2_09), acc);
            }
        }
        if (lane == 0) red[wid] = acc;
        __syncthreads();
        if (tid == 0) {
            float s = 0.0f;
            #pragma unroll
            for (int w = 0; w < NWARP; w++) s += red[w];
            red[NWARP] = s;
        }
        __syncthreads();
        carry = red[NWARP];
    }

    // ---- main loop: 32-row sub-tiles, rows register-resident, ONE bar each ----
    int buf = 0;
    for (int sub = 0; sub < NSUB; sub++) {
        int r0 = sub * SUBROWS;
        int rows_this = CHUNK - r0;
        if (rows_this > SUBROWS) rows_this = SUBROWS;

        int wr0 = 2 * wid, wr1 = 2 * wid + 1;       // this warp's local rows
        bool h0 = wr0 < rows_this, h1 = wr1 < rows_this;
        unsigned idx0 = (unsigned)(row0 + r0 + wr0) * F_DIM;
        unsigned idx1 = (unsigned)(row0 + r0 + wr1) * F_DIM;

        // load 2 rows into registers, fused square-sum
        float v0[6], v1[6];
        float s0 = 0.0f, s1 = 0.0f;
        #pragma unroll
        for (int k = 0; k < 6; k++) {
            int f = lane + 32 * k;
            bool inr = f < F_DIM;
            v0[k] = (h0 && inr) ? __ldg(mag + idx0 + f) : 0.0f;
            v1[k] = (h1 && inr) ? __ldg(mag + idx1 + f) : 0.0f;
            s0 = fmaf(v0[k], v0[k], s0);
            s1 = fmaf(v1[k], v1[k], s1);
        }
        #pragma unroll
        for (int off = 16; off > 0; off >>= 1) {
            s0 += __shfl_xor_sync(0xffffffffu, s0, off);
            s1 += __shfl_xor_sync(0xffffffffu, s1, off);
        }
        // lane 0 holds m[0] (v[0]) and m[160] (v[5]); finish x and publish
        if (lane == 0) {
            if (h0) {
                float sp = (2.0f * s0 - v0[0] * v0[0] - v0[5] * v0[5]) * (1.0f / 320.0f);
                sx[buf][wr0] = sqrtf(sp);
            }
            if (h1) {
                float sp = (2.0f * s1 - v1[0] * v1[0] - v1[5] * v1[5]) * (1.0f / 320.0f);
                sx[buf][wr1] = sqrtf(sp);
            }
        }
        __syncthreads();   // the only barrier per sub-tile

        // every warp redundantly scans the 32 rows (identical result)
        float xv = sx[buf][lane];
        bool valid = lane < rows_this;
        int t = c * CHUNK + r0 + lane;              // within-batch time
        float A, Bv;
        if (!valid)      { A = 1.0f; Bv = 0.0f; }   // identity padding
        else if (t == 0) { A = 0.0f; Bv = xv; }     // frame-0 passthrough
        else             { A = 0.9f; Bv = 0.1f * xv; }
        #pragma unroll
        for (int off = 1; off < 32; off <<= 1) {
            float Ap = __shfl_up_sync(0xffffffffu, A, off);
            float Bp = __shfl_up_sync(0xffffffffu, Bv, off);
            if (lane >= off) { Bv = fmaf(A, Bp, Bv); A *= Ap; }
        }
        float g = fmaf(A, carry, Bv);
        carry = __shfl_sync(0xffffffffu, g, 31);    // identity-padded => correct

        if (wid == 0 && valid) out_gain[row0 + r0 + lane] = g;

        float invg = __fdividef(1.0f, g + 0.001f);
        float inv0 = __shfl_sync(0xffffffffu, invg, wr0);
        float inv1 = __shfl_sync(0xffffffffu, invg, wr1);

        // multiply register data and store
        #pragma unroll
        for (int k = 0; k < 6; k++) {
            int f = lane + 32 * k;
            bool inr = f < F_DIM;
            if (h0 && inr) out[idx0 + f] = v0[k] * inv0;
            if (h1 && inr) out[idx1 + f] = v1[k] * inv1;
        }
        buf ^= 1;
    }
}

// ---------------------------------------------------------------------------
extern "C" void kernel_launch(void* const* d_in, const int* in_sizes, int n_in,
                              void* d_out, int out_size) {
    const float* mag = (const float*)d_in[0];
    float* out = (float*)d_out;
    float* out_gain = out + NEW_MAG_ELEMS;

    k_agc<<<NBLK, THREADS>>>(mag, out, out_gain);
}

// round 16
// speedup vs baseline: 1.5285x; 1.2574x over previous
#include <cuda_runtime.h>
#include <math.h>

// Problem shape (fixed by the dataset)
#define B_DIM 48
#define T_DIM 5000
#define F_DIM 161
#define BT (B_DIM * T_DIM)                  // 240000 rows
#define NEW_MAG_ELEMS ((size_t)BT * F_DIM)  // 38,640,000

#define CPB 9                       // chunks per batch (variable 555/556 rows)
#define NBLK (B_DIM * CPB)          // 432 = 144 SMs x 3 blocks: tail-free wave
#define THREADS 512
#define NWARP (THREADS / 32)        // 16
#define SUBROWS 32                  // rows per sub-tile = NWARP * 2
#define WARM 200                    // warmup rows; 0.9^200 ~ 7e-10 << 1e-3

#define LOG2_09 (-0.15200309344504997f)

__global__ void __launch_bounds__(THREADS, 3) k_agc(
    const float* __restrict__ mag,
    float* __restrict__ out,
    float* __restrict__ out_gain)
{
    __shared__ float sx[2][SUBROWS];    // double-buffered per-sub-tile x values
    __shared__ float red[NWARP + 1];

    int tid = threadIdx.x;
    int wid = tid >> 5, lane = tid & 31;
    int b = blockIdx.x / CPB;
    int c = blockIdx.x % CPB;

    int t_start = (c * T_DIM) / CPB;          // within-batch start frame
    int t_end   = ((c + 1) * T_DIM) / CPB;    // within-batch end frame (excl)
    int chunk_rows = t_end - t_start;         // 555 or 556
    int row0 = b * T_DIM + t_start;           // global row of chunk start

    float carry = 0.0f;

    // ---- warmup: weighted reduction over the 200 rows before the chunk ----
    // carry ~= sum_r 0.1 * 0.9^(WARM-1-r) * x[row0-WARM+r]  (c>0 => in-batch)
    if (c > 0) {
        float acc = 0.0f;
        for (int r = wid; r < WARM; r += NWARP) {
            const float* m = mag + (size_t)(row0 - WARM + r) * F_DIM;
            float s = 0.0f;
            #pragma unroll
            for (int f = lane; f < F_DIM; f += 32) {
                float v = m[f];
                s = fmaf(v, v, s);
            }
            #pragma unroll
            for (int off = 16; off > 0; off >>= 1)
                s += __shfl_xor_sync(0xffffffffu, s, off);
            if (lane == 0) {
                float m0 = m[0];
                float mN = m[F_DIM - 1];
                float sp = (2.0f * s - m0 * m0 - mN * mN) * (1.0f / 320.0f);
                acc = fmaf(sqrtf(sp),
                           0.1f * exp2f((float)(WARM - 1 - r) * LOG2_09), acc);
            }
        }
        if (lane == 0) red[wid] = acc;
        __syncthreads();
        if (tid == 0) {
            float s = 0.0f;
            #pragma unroll
            for (int w = 0; w < NWARP; w++) s += red[w];
            red[NWARP] = s;
        }
        __syncthreads();
        carry = red[NWARP];
    }

    // ---- main loop: 32-row sub-tiles, rows register-resident, ONE bar each ----
    int buf = 0;
    for (int r0 = 0; r0 < chunk_rows; r0 += SUBROWS) {
        int rows_this = chunk_rows - r0;
        if (rows_this > SUBROWS) rows_this = SUBROWS;

        int wr0 = 2 * wid, wr1 = 2 * wid + 1;       // this warp's local rows
        bool h0 = wr0 < rows_this, h1 = wr1 < rows_this;
        unsigned idx0 = (unsigned)(row0 + r0 + wr0) * F_DIM;
        unsigned idx1 = (unsigned)(row0 + r0 + wr1) * F_DIM;

        // load 2 rows into registers, fused square-sum
        float v0[6], v1[6];
        float s0 = 0.0f, s1 = 0.0f;
        #pragma unroll
        for (int k = 0; k < 6; k++) {
            int f = lane + 32 * k;
            bool inr = f < F_DIM;
            v0[k] = (h0 && inr) ? __ldg(mag + idx0 + f) : 0.0f;
            v1[k] = (h1 && inr) ? __ldg(mag + idx1 + f) : 0.0f;
            s0 = fmaf(v0[k], v0[k], s0);
            s1 = fmaf(v1[k], v1[k], s1);
        }
        #pragma unroll
        for (int off = 16; off > 0; off >>= 1) {
            s0 += __shfl_xor_sync(0xffffffffu, s0, off);
            s1 += __shfl_xor_sync(0xffffffffu, s1, off);
        }
        // lane 0 holds m[0] (v[0]) and m[160] (v[5]); finish x and publish
        if (lane == 0) {
            if (h0) {
                float sp = (2.0f * s0 - v0[0] * v0[0] - v0[5] * v0[5]) * (1.0f / 320.0f);
                sx[buf][wr0] = sqrtf(sp);
            }
            if (h1) {
                float sp = (2.0f * s1 - v1[0] * v1[0] - v1[5] * v1[5]) * (1.0f / 320.0f);
                sx[buf][wr1] = sqrtf(sp);
            }
        }
        __syncthreads();   // the only barrier per sub-tile

        // every warp redundantly scans the 32 rows (identical result)
        float xv = sx[buf][lane];
        bool valid = lane < rows_this;
        int t = t_start + r0 + lane;                // within-batch time
        float A, Bv;
        if (!valid)      { A = 1.0f; Bv = 0.0f; }   // identity padding
        else if (t == 0) { A = 0.0f; Bv = xv; }     // frame-0 passthrough
        else             { A = 0.9f; Bv = 0.1f * xv; }
        #pragma unroll
        for (int off = 1; off < 32; off <<= 1) {
            float Ap = __shfl_up_sync(0xffffffffu, A, off);
            float Bp = __shfl_up_sync(0xffffffffu, Bv, off);
            if (lane >= off) { Bv = fmaf(A, Bp, Bv); A *= Ap; }
        }
        float g = fmaf(A, carry, Bv);
        carry = __shfl_sync(0xffffffffu, g, 31);    // identity-padded => correct

        if (wid == 0 && valid) out_gain[row0 + r0 + lane] = g;

        float invg = __fdividef(1.0f, g + 0.001f);
        float inv0 = __shfl_sync(0xffffffffu, invg, wr0);
        float inv1 = __shfl_sync(0xffffffffu, invg, wr1);

        // multiply register data and store
        #pragma unroll
        for (int k = 0; k < 6; k++) {
            int f = lane + 32 * k;
            bool inr = f < F_DIM;
            if (h0 && inr) out[idx0 + f] = v0[k] * inv0;
            if (h1 && inr) out[idx1 + f] = v1[k] * inv1;
        }
        buf ^= 1;
    }
}

// ---------------------------------------------------------------------------
extern "C" void kernel_launch(void* const* d_in, const int* in_sizes, int n_in,
                              void* d_out, int out_size) {
    const float* mag = (const float*)d_in[0];
    float* out = (float*)d_out;
    float* out_gain = out + NEW_MAG_ELEMS;

    k_agc<<<NBLK, THREADS>>>(mag, out, out_gain);
}

// round 17
// speedup vs baseline: 1.7135x; 1.1210x over previous
#include <cuda_runtime.h>
#include <math.h>

// Problem shape (fixed by the dataset)
#define B_DIM 48
#define T_DIM 5000
#define F_DIM 161
#define BT (B_DIM * T_DIM)                  // 240000 rows
#define NEW_MAG_ELEMS ((size_t)BT * F_DIM)  // 38,640,000

#define CPB 9                       // chunks per batch (variable 555/556 rows)
#define NBLK (B_DIM * CPB)          // 432 = 144 SMs x 3 blocks: tail-free wave
#define THREADS 512
#define NWARP (THREADS / 32)        // 16
#define SUBROWS 32                  // rows per sub-tile = NWARP * 2
#define WARM 100                    // warmup rows; 0.9^100 ~ 2.7e-5 << 1e-3

#define LOG2_09 (-0.15200309344504997f)

__global__ void __launch_bounds__(THREADS, 3) k_agc(
    const float* __restrict__ mag,
    float* __restrict__ out,
    float* __restrict__ out_gain)
{
    __shared__ float sx[2][SUBROWS];    // double-buffered per-sub-tile x values
    __shared__ float red[NWARP + 1];

    int tid = threadIdx.x;
    int wid = tid >> 5, lane = tid & 31;
    int b = blockIdx.x / CPB;
    int c = blockIdx.x % CPB;

    int t_start = (c * T_DIM) / CPB;          // within-batch start frame
    int t_end   = ((c + 1) * T_DIM) / CPB;    // within-batch end frame (excl)
    int chunk_rows = t_end - t_start;         // 555 or 556
    int row0 = b * T_DIM + t_start;           // global row of chunk start

    float carry = 0.0f;

    // ---- warmup: weighted reduction over the 100 rows before the chunk ----
    // carry ~= sum_r 0.1 * 0.9^(WARM-1-r) * x[row0-WARM+r]  (c>0 => in-batch)
    if (c > 0) {
        float acc = 0.0f;
        for (int r = wid; r < WARM; r += NWARP) {
            const float* m = mag + (size_t)(row0 - WARM + r) * F_DIM;
            float s = 0.0f;
            #pragma unroll
            for (int k = 0; k < 5; k++) {
                float v = m[lane + 32 * k];          // f <= 159 < 161 always
                s = fmaf(v, v, s);
            }
            float mN = m[F_DIM - 1];
            if (lane == 0) s = fmaf(mN, mN, s);      // element 160 once
            #pragma unroll
            for (int off = 16; off > 0; off >>= 1)
                s += __shfl_xor_sync(0xffffffffu, s, off);
            if (lane == 0) {
                float m0 = m[0];
                float sp = (2.0f * s - m0 * m0 - mN * mN) * (1.0f / 320.0f);
                acc = fmaf(sqrtf(sp),
                           0.1f * exp2f((float)(WARM - 1 - r) * LOG2_09), acc);
            }
        }
        if (lane == 0) red[wid] = acc;
        __syncthreads();
        if (tid == 0) {
            float s = 0.0f;
            #pragma unroll
            for (int w = 0; w < NWARP; w++) s += red[w];
            red[NWARP] = s;
        }
        __syncthreads();
        carry = red[NWARP];
    }

    // ---- main loop: 32-row sub-tiles, rows register-resident, ONE bar each ----
    int buf = 0;
    for (int r0 = 0; r0 < chunk_rows; r0 += SUBROWS) {
        int rows_this = chunk_rows - r0;
        if (rows_this > SUBROWS) rows_this = SUBROWS;

        int wr0 = 2 * wid, wr1 = 2 * wid + 1;       // this warp's local rows
        bool h0 = wr0 < rows_this, h1 = wr1 < rows_this;
        unsigned idx0 = (unsigned)(row0 + r0 + wr0) * F_DIM;
        unsigned idx1 = (unsigned)(row0 + r0 + wr1) * F_DIM;

        // load 2 rows into registers (5 full strides + element 160)
        float v0[5], v1[5], last0, last1;
        float s0 = 0.0f, s1 = 0.0f;
        #pragma unroll
        for (int k = 0; k < 5; k++) {
            int f = lane + 32 * k;                   // always < 161
            v0[k] = h0 ? __ldg(mag + idx0 + f) : 0.0f;
            v1[k] = h1 ? __ldg(mag + idx1 + f) : 0.0f;
            s0 = fmaf(v0[k], v0[k], s0);
            s1 = fmaf(v1[k], v1[k], s1);
        }
        last0 = (h0 && lane == 0) ? __ldg(mag + idx0 + F_DIM - 1) : 0.0f;
        last1 = (h1 && lane == 0) ? __ldg(mag + idx1 + F_DIM - 1) : 0.0f;
        s0 = fmaf(last0, last0, s0);
        s1 = fmaf(last1, last1, s1);
        #pragma unroll
        for (int off = 16; off > 0; off >>= 1) {
            s0 += __shfl_xor_sync(0xffffffffu, s0, off);
            s1 += __shfl_xor_sync(0xffffffffu, s1, off);
        }
        // lane 0 holds m[0] (v[0]) and m[160] (last); finish x and publish
        if (lane == 0) {
            if (h0) {
                float sp = (2.0f * s0 - v0[0] * v0[0] - last0 * last0) * (1.0f / 320.0f);
                sx[buf][wr0] = sqrtf(sp);
            }
            if (h1) {
                float sp = (2.0f * s1 - v1[0] * v1[0] - last1 * last1) * (1.0f / 320.0f);
                sx[buf][wr1] = sqrtf(sp);
            }
        }
        __syncthreads();   // the only barrier per sub-tile

        // every warp redundantly scans the 32 rows (identical result)
        float xv = sx[buf][lane];
        bool valid = lane < rows_this;
        int t = t_start + r0 + lane;                // within-batch time
        float A, Bv;
        if (!valid)      { A = 1.0f; Bv = 0.0f; }   // identity padding
        else if (t == 0) { A = 0.0f; Bv = xv; }     // frame-0 passthrough
        else             { A = 0.9f; Bv = 0.1f * xv; }
        #pragma unroll
        for (int off = 1; off < 32; off <<= 1) {
            float Ap = __shfl_up_sync(0xffffffffu, A, off);
            float Bp = __shfl_up_sync(0xffffffffu, Bv, off);
            if (lane >= off) { Bv = fmaf(A, Bp, Bv); A *= Ap; }
        }
        float g = fmaf(A, carry, Bv);
        carry = __shfl_sync(0xffffffffu, g, 31);    // identity-padded => correct

        if (wid == 0 && valid) out_gain[row0 + r0 + lane] = g;

        float invg = __fdividef(1.0f, g + 0.001f);
        float inv0 = __shfl_sync(0xffffffffu, invg, wr0);
        float inv1 = __shfl_sync(0xffffffffu, invg, wr1);

        // multiply register data and store (streaming)
        #pragma unroll
        for (int k = 0; k < 5; k++) {
            int f = lane + 32 * k;
            if (h0) __stcs(out + idx0 + f, v0[k] * inv0);
            if (h1) __stcs(out + idx1 + f, v1[k] * inv1);
        }
        if (h0 && lane == 0) __stcs(out + idx0 + F_DIM - 1, last0 * inv0);
        if (h1 && lane == 0) __stcs(out + idx1 + F_DIM - 1, last1 * inv1);
        buf ^= 1;
    }
}

// ---------------------------------------------------------------------------
extern "C" void kernel_launch(void* const* d_in, const int* in_sizes, int n_in,
                              void* d_out, int out_size) {
    const float* mag = (const float*)d_in[0];
    float* out = (float*)d_out;
    float* out_gain = out + NEW_MAG_ELEMS;

    k_agc<<<NBLK, THREADS>>>(mag, out, out_gain);
}